// round 13
// baseline (speedup 1.0000x reference)
#include <cuda_runtime.h>
#include <cuda_fp16.h>
#include <cstdint>

// ---------------- problem constants ----------------
constexpr int NT  = 16384;   // tokens
constexpr int NH  = 2048;    // hidden
constexpr int NE  = 64;      // experts
constexpr int CAP = 512;     // 2*ceil(NT/NE)

constexpr int BM   = 128;    // tokens per CTA
constexpr int CH   = 32;     // k per chunk
constexpr int NCH  = NH / CH;       // 64 chunks
constexpr int NCTA = NT / BM;       // 128

constexpr int NTHR = 320;           // 8 consumer warps + 2 producer warps

constexpr int AROW  = 80;           // bytes per smem row: 32 fp16 (64B) + 16B pad
constexpr int ACOMP = BM * AROW;    // 10240 B per A component tile
constexpr int BCOMP = NE * AROW;    // 5120 B per B component tile
constexpr int BUFB  = 2 * ACOMP + 2 * BCOMP;  // 30720 per buffer
constexpr int SMEM_BYTES = 2 * BUFB;          // 61440 (dynamic)

constexpr int BCHUNK_BYTES = 2 * BCOMP;         // 10240 per chunk in d_Bp
constexpr int BCHUNK_I4    = BCHUNK_BYTES / 16; // 640

constexpr float SCALE   = 2048.0f;                // 2^11 (exact)
constexpr float DESCALE = 2.384185791015625e-07f; // 2^-22

// ---------------- device scratch ----------------
__device__ __align__(16) char d_Bp[NCH * BCHUNK_BYTES];  // pre-split, scaled B tiles
__device__ int4               d_tok[NT];
__device__ unsigned long long d_bkt1[NE * NT];
__device__ unsigned long long d_bkt2[NE * NT];
__device__ int                d_cnt1[NE];
__device__ int                d_cnt2[NE];
__device__ unsigned char      d_keep[2 * NT];

// ---------------- helpers ----------------
__device__ __forceinline__ void mma_fp16(float* d, const unsigned* a, const unsigned* b) {
    asm volatile("mma.sync.aligned.m16n8k16.row.col.f32.f16.f16.f32 "
        "{%0,%1,%2,%3}, {%4,%5,%6,%7}, {%8,%9}, {%0,%1,%2,%3};"
        : "+f"(d[0]), "+f"(d[1]), "+f"(d[2]), "+f"(d[3])
        : "r"(a[0]), "r"(a[1]), "r"(a[2]), "r"(a[3]), "r"(b[0]), "r"(b[1]));
}
__device__ __forceinline__ void mma_fp16_z(float* d, const unsigned* a, const unsigned* b) {
    asm volatile("mma.sync.aligned.m16n8k16.row.col.f32.f16.f16.f32 "
        "{%0,%1,%2,%3}, {%4,%5,%6,%7}, {%8,%9}, {%10,%10,%10,%10};"
        : "=f"(d[0]), "=f"(d[1]), "=f"(d[2]), "=f"(d[3])
        : "r"(a[0]), "r"(a[1]), "r"(a[2]), "r"(a[3]), "r"(b[0]), "r"(b[1]), "f"(0.f));
}
__device__ __forceinline__ unsigned h2u(__half2 h) { return *(unsigned*)&h; }

// ---------------- kernel P: split scaled W into 2 fp16 components ----------------
// Also zeroes counters and pre-initializes d_keep to 1 (k_rank writes only drops).
__global__ __launch_bounds__(256) void k_prepB(const float* __restrict__ W) {
    const int ch  = blockIdx.x;                 // 0..63
    const int tid = threadIdx.x;
    if (ch == 0 && tid < NE) { d_cnt1[tid] = 0; d_cnt2[tid] = 0; }
    {
        const int g = ch * 256 + tid;
        ((unsigned short*)d_keep)[g] = 0x0101;
    }
    const int e   = tid >> 2;                   // expert row
    const int kl0 = (tid & 3) * 8;              // k base within chunk
    char* dst = d_Bp + (size_t)ch * BCHUNK_BYTES + e * AROW + kl0 * 2;
#pragma unroll
    for (int i = 0; i < 8; i += 2) {
        const int k = ch * CH + kl0 + i;
        const float x0 = W[(size_t)k * NE + e] * SCALE;
        const float x1 = W[(size_t)(k + 1) * NE + e] * SCALE;
        const __half2 c0 = __floats2half2_rn(x0, x1);
        const float r0 = x0 - __low2float(c0), r1 = x1 - __high2float(c0);
        const __half2 c1 = __floats2half2_rn(r0, r1);
        *(unsigned*)(dst + i * 2)         = h2u(c0);
        *(unsigned*)(dst + BCOMP + i * 2) = h2u(c1);
    }
}

// ---------------- kernel 1: warp-specialized HMMA emulated-fp32 GEMM + routing ----------------
// Warps 0-7: consumers (LDS + MMA only).  Warps 8-9: producers (LDG + convert + STS).
__global__ __launch_bounds__(NTHR, 1) void k_gemm_route(const float* __restrict__ X) {
    extern __shared__ __align__(16) char smem[];
    float* Cs = (float*)smem;                 // [128][65] overlay after mainloop

    const int tid  = threadIdx.x;
    const int lane = tid & 31;
    const int wid  = tid >> 5;
    const int t0   = blockIdx.x * BM;
    const bool is_prod = (tid >= 256);

    // ======================= producer state =======================
    const int p = tid - 256;                  // 0..63 (producers only)
    const float* xrow0 = X + (size_t)(t0 + (p < 0 ? 0 : p) * 2) * NH;       // row 2p
    const float* xrow1 = xrow0 + NH;                                         // row 2p+1
    const int4* bsrc = (const int4*)d_Bp;

    float4 xa[8], xb[8];   // two full rows of one chunk (32 floats each)
    int4   bv[10];         // B chunk slice: 10 int4 per producer

    // convert regs (rows 2p,2p+1 of some chunk) into buffer `buf`
    auto produce = [&](int buf) {
        char* base  = smem + buf * BUFB;
        char* ar0   = base + (p * 2) * AROW;
        char* ar1   = base + (p * 2 + 1) * AROW;
#pragma unroll
        for (int i = 0; i < 8; ++i) {
            {   // row 2p
                const float4 v = xa[i];
                const float sx = v.x * SCALE, sy = v.y * SCALE;
                const float sz = v.z * SCALE, sw = v.w * SCALE;
                const __half2 a0 = __floats2half2_rn(sx, sy);
                const float r0 = sx - __low2float(a0), r1 = sy - __high2float(a0);
                const __half2 a1 = __floats2half2_rn(r0, r1);
                const __half2 b0 = __floats2half2_rn(sz, sw);
                const float q0 = sz - __low2float(b0), q1 = sw - __high2float(b0);
                const __half2 b1 = __floats2half2_rn(q0, q1);
                *(uint2*)(ar0 + i * 8)         = make_uint2(h2u(a0), h2u(b0));
                *(uint2*)(ar0 + ACOMP + i * 8) = make_uint2(h2u(a1), h2u(b1));
            }
            {   // row 2p+1
                const float4 v = xb[i];
                const float sx = v.x * SCALE, sy = v.y * SCALE;
                const float sz = v.z * SCALE, sw = v.w * SCALE;
                const __half2 a0 = __floats2half2_rn(sx, sy);
                const float r0 = sx - __low2float(a0), r1 = sy - __high2float(a0);
                const __half2 a1 = __floats2half2_rn(r0, r1);
                const __half2 b0 = __floats2half2_rn(sz, sw);
                const float q0 = sz - __low2float(b0), q1 = sw - __high2float(b0);
                const __half2 b1 = __floats2half2_rn(q0, q1);
                *(uint2*)(ar1 + i * 8)         = make_uint2(h2u(a0), h2u(b0));
                *(uint2*)(ar1 + ACOMP + i * 8) = make_uint2(h2u(a1), h2u(b1));
            }
        }
        char* bbase = base + 2 * ACOMP;
#pragma unroll
        for (int j = 0; j < 10; ++j)
            *(int4*)(bbase + (p + j * 64) * 16) = bv[j];
    };
    auto prefetch = [&](int ch) {
        const float4* x0 = (const float4*)(xrow0 + ch * CH);
        const float4* x1 = (const float4*)(xrow1 + ch * CH);
#pragma unroll
        for (int i = 0; i < 8; ++i) { xa[i] = x0[i]; xb[i] = x1[i]; }
        const int4* bs = bsrc + (size_t)ch * BCHUNK_I4;
#pragma unroll
        for (int j = 0; j < 10; ++j) bv[j] = bs[p + j * 64];
    };

    // ======================= prologue =======================
    if (is_prod) {
        prefetch(0);
        produce(0);
        prefetch(1);
    }

    // consumer accumulators
    float acc[8][4];    // master fp32 sum (IEEE FADD promoted)
    float accS[8][4];   // persistent cross-term accumulator (~2^-12 scale)
#pragma unroll
    for (int j = 0; j < 8; ++j)
#pragma unroll
        for (int q = 0; q < 4; ++q) { acc[j][q] = 0.f; accS[j][q] = 0.f; }

    const int r0w = (wid & 7) * 16 + (lane >> 2);   // A fragment row (consumers)
    const int kq  = (lane & 3) * 2;                 // fragment k offset
    const int bn  = lane >> 2;                      // B fragment n offset within tile

    __syncthreads();

    // ======================= mainloop =======================
    for (int ch = 0; ch < NCH; ++ch) {
        if (!is_prod) {
            const char* base = smem + (ch & 1) * BUFB;
            float accB[8][4];
#pragma unroll
            for (int ks = 0; ks < 2; ++ks) {
                unsigned a[2][4];
#pragma unroll
                for (int c = 0; c < 2; ++c) {
                    const char* ab = base + c * ACOMP;
                    a[c][0] = *(const unsigned*)(ab + r0w * AROW + (ks * 16 + kq) * 2);
                    a[c][1] = *(const unsigned*)(ab + (r0w + 8) * AROW + (ks * 16 + kq) * 2);
                    a[c][2] = *(const unsigned*)(ab + r0w * AROW + (ks * 16 + kq + 8) * 2);
                    a[c][3] = *(const unsigned*)(ab + (r0w + 8) * AROW + (ks * 16 + kq + 8) * 2);
                }
                unsigned b[8][2];
                // B component 0
#pragma unroll
                for (int j = 0; j < 8; ++j) {
                    const char* bnp = base + 2 * ACOMP + (j * 8 + bn) * AROW;
                    b[j][0] = *(const unsigned*)(bnp + (ks * 16 + kq) * 2);
                    b[j][1] = *(const unsigned*)(bnp + (ks * 16 + kq + 8) * 2);
                }
                if (ks == 0) {
#pragma unroll
                    for (int j = 0; j < 8; ++j) mma_fp16_z(accB[j], a[0], b[j]);  // h0*d0 reset
                } else {
#pragma unroll
                    for (int j = 0; j < 8; ++j) mma_fp16(accB[j], a[0], b[j]);    // h0*d0
                }
#pragma unroll
                for (int j = 0; j < 8; ++j) mma_fp16(accS[j], a[1], b[j]);        // h1*d0
                // B component 1
#pragma unroll
                for (int j = 0; j < 8; ++j) {
                    const char* bnp = base + 2 * ACOMP + BCOMP + (j * 8 + bn) * AROW;
                    b[j][0] = *(const unsigned*)(bnp + (ks * 16 + kq) * 2);
                    b[j][1] = *(const unsigned*)(bnp + (ks * 16 + kq + 8) * 2);
                }
#pragma unroll
                for (int j = 0; j < 8; ++j) mma_fp16(accS[j], a[0], b[j]);        // h0*d1
            }
            // promote chunk partial with IEEE fp32 adds
#pragma unroll
            for (int j = 0; j < 8; ++j)
#pragma unroll
                for (int q = 0; q < 4; ++q) acc[j][q] += accB[j][q];
        } else {
            if (ch + 1 < NCH) {
                produce((ch + 1) & 1);
                if (ch + 2 < NCH) prefetch(ch + 2);
            }
        }
        __syncthreads();
    }

    // fold cross terms, undo 2^22 scaling; write Cs (consumers only)
    if (!is_prod) {
#pragma unroll
        for (int j = 0; j < 8; ++j)
#pragma unroll
            for (int q = 0; q < 4; ++q) acc[j][q] = (acc[j][q] + accS[j][q]) * DESCALE;
        const int cr = (wid & 7) * 16 + (lane >> 2);
        const int cq = (lane & 3) * 2;
#pragma unroll
        for (int j = 0; j < 8; ++j) {
            Cs[cr * 65 + j * 8 + cq]           = acc[j][0];
            Cs[cr * 65 + j * 8 + cq + 1]       = acc[j][1];
            Cs[(cr + 8) * 65 + j * 8 + cq]     = acc[j][2];
            Cs[(cr + 8) * 65 + j * 8 + cq + 1] = acc[j][3];
        }
    }
    __syncthreads();

    // ---- per-token epilogue: softmax + top1/top2 + bucket insert ----
    if (tid < BM) {
        const int t = t0 + tid;
        const float* row = Cs + tid * 65;
        float m0 = row[0]; int i1 = 0;
#pragma unroll
        for (int e = 1; e < NE; ++e) { float l = row[e]; if (l > m0) { m0 = l; i1 = e; } }
        float m2 = -3.402823466e+38f; int i2 = 0;
#pragma unroll
        for (int e = 0; e < NE; ++e) {
            if (e == i1) continue;
            float l = row[e];
            if (l > m2) { m2 = l; i2 = e; }
        }
        float Z = 0.f;
#pragma unroll
        for (int e = 0; e < NE; ++e) Z += expf(row[e] - m0);
        const float p1 = 1.0f / Z;
        const float p2 = expf(m2 - m0) / Z;

        d_tok[t] = make_int4(i1, i2, __float_as_int(p1), __float_as_int(p2));
        const unsigned long long c =
            ((unsigned long long)__float_as_uint(p1) << 32) |
            (unsigned long long)(0xFFFFFFFFu - (unsigned)t);
        int pos1 = atomicAdd(&d_cnt1[i1], 1);
        d_bkt1[(size_t)i1 * NT + pos1] = c;
        int pos2 = atomicAdd(&d_cnt2[i2], 1);
        d_bkt2[(size_t)i2 * NT + pos2] = c;
    }
}

// ---------------- kernel 2: per-expert capacity ranking (drop-only writes) ----------------
__global__ __launch_bounds__(256) void k_rank() {
    __shared__ unsigned long long s[2048];   // 16KB
    const int bid    = blockIdx.x;
    const int e      = bid & 63;
    const bool second = (bid >= NE);
    const int n      = second ? d_cnt2[e] : d_cnt1[e];
    const unsigned long long* list = (second ? d_bkt2 : d_bkt1) + (size_t)e * NT;
    const int offset = second ? d_cnt1[e] : 0;
    unsigned char* keep = d_keep + (second ? NT : 0);

    if (n + offset <= CAP) return;             // all fit: keep already 1
    if (offset >= CAP) {                       // everything drops
        for (int i = threadIdx.x; i < n; i += blockDim.x)
            keep[(int)(0xFFFFFFFFu - (unsigned)list[i])] = 0;
        return;
    }
    if (n <= 2048) {
        for (int i = threadIdx.x; i < n; i += blockDim.x) s[i] = list[i];
        __syncthreads();
        for (int i = threadIdx.x; i < n; i += blockDim.x) {
            const unsigned long long ci = s[i];
            int r = 0;
            for (int j = 0; j < n; ++j) r += (s[j] > ci);
            if (r + offset >= CAP)
                keep[(int)(0xFFFFFFFFu - (unsigned)ci)] = 0;
        }
    } else {
        for (int i = threadIdx.x; i < n; i += blockDim.x) {
            const unsigned long long ci = list[i];
            int r = 0;
            for (int j = 0; j < n; ++j) r += (list[j] > ci);
            if (r + offset >= CAP)
                keep[(int)(0xFFFFFFFFu - (unsigned)ci)] = 0;
        }
    }
}

// ---------------- kernel 3: finalize outputs (2 tokens per thread) ----------------
__global__ __launch_bounds__(256) void k_finalize(float* __restrict__ out) {
    const int gid0 = blockIdx.x * blockDim.x + threadIdx.x;
    float4* o = (float4*)out;
#pragma unroll
    for (int u = 0; u < 2; ++u) {
        const int gid = gid0 + u * (NT * 8);
        const int t = gid >> 4;
        const int c = gid & 15;
        const int4 rec = d_tok[t];
        const float p1 = __int_as_float(rec.z);
        const float p2 = __int_as_float(rec.w);
        const bool k1 = d_keep[t] != 0;
        const bool k2 = d_keep[NT + t] != 0;
        const float p1k = k1 ? p1 : 0.f;
        const float p2k = k2 ? p2 : 0.f;
        const float denom = fmaxf(p1k + p2k, 1.1920929e-07f);
        const float g1 = p1k / denom;
        const float g2 = p2k / denom;
        const float m1 = k1 ? 1.0f : 0.0f;

        const int e0 = c * 4;
        float4 m, pp;
        m.x = (rec.x == e0 + 0) ? m1 : 0.f;
        m.y = (rec.x == e0 + 1) ? m1 : 0.f;
        m.z = (rec.x == e0 + 2) ? m1 : 0.f;
        m.w = (rec.x == e0 + 3) ? m1 : 0.f;
        pp.x = (rec.x == e0 + 0) ? g1 : ((rec.y == e0 + 0) ? g2 : 0.f);
        pp.y = (rec.x == e0 + 1) ? g1 : ((rec.y == e0 + 1) ? g2 : 0.f);
        pp.z = (rec.x == e0 + 2) ? g1 : ((rec.y == e0 + 2) ? g2 : 0.f);
        pp.w = (rec.x == e0 + 3) ? g1 : ((rec.y == e0 + 3) ? g2 : 0.f);

        o[(size_t)t * 16 + c] = m;
        o[(size_t)NT * 16 + (size_t)t * 16 + c] = pp;
    }
}

// ---------------- launch ----------------
extern "C" void kernel_launch(void* const* d_in, const int* in_sizes, int n_in,
                              void* d_out, int out_size) {
    (void)in_sizes; (void)n_in; (void)out_size;
    const float* X = (const float*)d_in[0];
    const float* W = (const float*)d_in[1];
    float* out = (float*)d_out;

    static bool attr_set = false;
    if (!attr_set) {
        cudaFuncSetAttribute(k_gemm_route, cudaFuncAttributeMaxDynamicSharedMemorySize, SMEM_BYTES);
        attr_set = true;
    }

    k_prepB<<<NCH, 256>>>(W);
    k_gemm_route<<<NCTA, NTHR, SMEM_BYTES>>>(X);
    k_rank<<<2 * NE, 256>>>();
    k_finalize<<<(NT * 8) / 256, 256>>>(out);
}

// round 14
// speedup vs baseline: 1.3848x; 1.3848x over previous
#include <cuda_runtime.h>
#include <cuda_fp16.h>
#include <cstdint>

// ---------------- problem constants ----------------
constexpr int NT  = 16384;   // tokens
constexpr int NH  = 2048;    // hidden
constexpr int NE  = 64;      // experts
constexpr int CAP = 512;     // 2*ceil(NT/NE)

constexpr int BM   = 128;    // tokens per CTA
constexpr int CH   = 64;     // k per chunk (doubled: amortize per-chunk overhead)
constexpr int NCH  = NH / CH;       // 32 chunks
constexpr int NCTA = NT / BM;       // 128

constexpr int AROW  = 144;          // bytes per smem row: 64 fp16 (128B) + 16B pad
constexpr int ACOMP = BM * AROW;    // 18432 B per A component tile
constexpr int BCOMP = NE * AROW;    // 9216 B per B component tile
constexpr int BUFB  = 2 * ACOMP + 2 * BCOMP;  // 55296 per buffer
constexpr int SMEM_BYTES = 2 * BUFB;          // 110592 (dynamic, needs opt-in)

constexpr int BCHUNK_BYTES = 2 * BCOMP;         // 18432 per chunk in d_Bp
constexpr int BCHUNK_I4    = BCHUNK_BYTES / 16; // 1152

constexpr float SCALE   = 2048.0f;                // 2^11 (exact)
constexpr float DESCALE = 2.384185791015625e-07f; // 2^-22

// ---------------- device scratch ----------------
__device__ __align__(16) char d_Bp[NCH * BCHUNK_BYTES];  // pre-split, scaled B tiles
__device__ int4               d_tok[NT];
__device__ unsigned long long d_bkt1[NE * NT];
__device__ unsigned long long d_bkt2[NE * NT];
__device__ int                d_cnt1[NE];
__device__ int                d_cnt2[NE];
__device__ unsigned char      d_keep[2 * NT];

// ---------------- helpers ----------------
__device__ __forceinline__ void mma_fp16(float* d, const unsigned* a, const unsigned* b) {
    asm volatile("mma.sync.aligned.m16n8k16.row.col.f32.f16.f16.f32 "
        "{%0,%1,%2,%3}, {%4,%5,%6,%7}, {%8,%9}, {%0,%1,%2,%3};"
        : "+f"(d[0]), "+f"(d[1]), "+f"(d[2]), "+f"(d[3])
        : "r"(a[0]), "r"(a[1]), "r"(a[2]), "r"(a[3]), "r"(b[0]), "r"(b[1]));
}
__device__ __forceinline__ void mma_fp16_z(float* d, const unsigned* a, const unsigned* b) {
    asm volatile("mma.sync.aligned.m16n8k16.row.col.f32.f16.f16.f32 "
        "{%0,%1,%2,%3}, {%4,%5,%6,%7}, {%8,%9}, {%10,%10,%10,%10};"
        : "=f"(d[0]), "=f"(d[1]), "=f"(d[2]), "=f"(d[3])
        : "r"(a[0]), "r"(a[1]), "r"(a[2]), "r"(a[3]), "r"(b[0]), "r"(b[1]), "f"(0.f));
}
__device__ __forceinline__ unsigned h2u(__half2 h) { return *(unsigned*)&h; }

// ---------------- kernel P: split scaled W into 2 fp16 components ----------------
// Also zeroes counters and pre-initializes d_keep to 1 (k_rank writes only drops).
__global__ __launch_bounds__(256) void k_prepB(const float* __restrict__ W) {
    const int ch  = blockIdx.x;                 // 0..31
    const int tid = threadIdx.x;
    if (ch == 0 && tid < NE) { d_cnt1[tid] = 0; d_cnt2[tid] = 0; }
    {   // init keep=1: 8192 threads x 4 bytes, coalesced (covers 2*NT bytes)
        const int g = ch * 256 + tid;
        ((unsigned*)d_keep)[g] = 0x01010101u;
    }
    const int e   = tid >> 2;                   // expert row
    const int kl0 = (tid & 3) * 16;             // k base within chunk (64 k / 4 threads)
    char* dst = d_Bp + (size_t)ch * BCHUNK_BYTES + e * AROW + kl0 * 2;
#pragma unroll
    for (int i = 0; i < 16; i += 2) {
        const int k = ch * CH + kl0 + i;
        const float x0 = W[(size_t)k * NE + e] * SCALE;
        const float x1 = W[(size_t)(k + 1) * NE + e] * SCALE;
        const __half2 c0 = __floats2half2_rn(x0, x1);
        const float r0 = x0 - __low2float(c0), r1 = x1 - __high2float(c0);
        const __half2 c1 = __floats2half2_rn(r0, r1);
        *(unsigned*)(dst + i * 2)         = h2u(c0);
        *(unsigned*)(dst + BCOMP + i * 2) = h2u(c1);
    }
}

// ---------------- kernel 1: pipelined HMMA emulated-fp32 GEMM (CH=64) + routing ----------------
__global__ __launch_bounds__(256, 1) void k_gemm_route(const float* __restrict__ X) {
    extern __shared__ __align__(16) char smem[];
    float* Cs = (float*)smem;                 // [128][65] overlay after mainloop

    const int tid  = threadIdx.x;
    const int lane = tid & 31;
    const int wid  = tid >> 5;
    const int t0   = blockIdx.x * BM;

    const int xr = tid >> 1;                  // token row (2 threads per row)
    const int xc = (tid & 1) * 32;            // 32-float half of the 64-k chunk
    const float4* xptr = (const float4*)(X + (size_t)(t0 + xr) * NH + xc);

    const int4* bsrc = (const int4*)d_Bp;

    float4 xv[8];
    int4   bv[5];

    // convert current xv/bv regs into buffer `buf`
    auto convert_store = [&](int buf) {
        char* base = smem + buf * BUFB;
        char* arow = base + xr * AROW + xc * 2;
#pragma unroll
        for (int i = 0; i < 8; ++i) {
            const float4 v = xv[i];
            const float sx = v.x * SCALE, sy = v.y * SCALE;
            const float sz = v.z * SCALE, sw = v.w * SCALE;
            const __half2 a0 = __floats2half2_rn(sx, sy);
            const float r0 = sx - __low2float(a0), r1 = sy - __high2float(a0);
            const __half2 a1 = __floats2half2_rn(r0, r1);
            const __half2 b0 = __floats2half2_rn(sz, sw);
            const float q0 = sz - __low2float(b0), q1 = sw - __high2float(b0);
            const __half2 b1 = __floats2half2_rn(q0, q1);
            *(uint2*)(arow + i * 8)         = make_uint2(h2u(a0), h2u(b0));
            *(uint2*)(arow + ACOMP + i * 8) = make_uint2(h2u(a1), h2u(b1));
        }
        char* bbase = base + 2 * ACOMP;
#pragma unroll
        for (int j = 0; j < 5; ++j) {
            int i = tid + j * 256;
            if (i < BCHUNK_I4) *(int4*)(bbase + i * 16) = bv[j];
        }
    };
    auto prefetch = [&](int ch) {
#pragma unroll
        for (int i = 0; i < 8; ++i) xv[i] = xptr[ch * 16 + i];
        const int4* bs = bsrc + (size_t)ch * BCHUNK_I4;
#pragma unroll
        for (int j = 0; j < 5; ++j) { int i = tid + j * 256; if (i < BCHUNK_I4) bv[j] = bs[i]; }
    };

    // prologue: chunk 0 -> regs -> buf0; prefetch chunk 1 regs
    prefetch(0);
    convert_store(0);
    prefetch(1);
    __syncthreads();

    float acc[8][4];    // master fp32 sum (IEEE FADD promoted)
    float accS[8][4];   // persistent cross-term accumulator (~2^-12 scale)
#pragma unroll
    for (int j = 0; j < 8; ++j)
#pragma unroll
        for (int q = 0; q < 4; ++q) { acc[j][q] = 0.f; accS[j][q] = 0.f; }

    const int r0w = wid * 16 + (lane >> 2);   // A fragment row
    const int kq  = (lane & 3) * 2;           // fragment k offset
    const int bn  = lane >> 2;                // B fragment n offset within tile

    for (int ch = 0; ch < NCH; ++ch) {
        const char* base = smem + (ch & 1) * BUFB;

        // ---- MMAs: h0d0 -> accB (fresh per chunk); h1d0, h0d1 -> accS ----
        float accB[8][4];
#pragma unroll
        for (int ks = 0; ks < 4; ++ks) {
            unsigned a[2][4];
#pragma unroll
            for (int c = 0; c < 2; ++c) {
                const char* ab = base + c * ACOMP;
                a[c][0] = *(const unsigned*)(ab + r0w * AROW + (ks * 16 + kq) * 2);
                a[c][1] = *(const unsigned*)(ab + (r0w + 8) * AROW + (ks * 16 + kq) * 2);
                a[c][2] = *(const unsigned*)(ab + r0w * AROW + (ks * 16 + kq + 8) * 2);
                a[c][3] = *(const unsigned*)(ab + (r0w + 8) * AROW + (ks * 16 + kq + 8) * 2);
            }
            unsigned b[8][2];
            // B component 0
#pragma unroll
            for (int j = 0; j < 8; ++j) {
                const char* bnp = base + 2 * ACOMP + (j * 8 + bn) * AROW;
                b[j][0] = *(const unsigned*)(bnp + (ks * 16 + kq) * 2);
                b[j][1] = *(const unsigned*)(bnp + (ks * 16 + kq + 8) * 2);
            }
            if (ks == 0) {
#pragma unroll
                for (int j = 0; j < 8; ++j) mma_fp16_z(accB[j], a[0], b[j]);   // h0*d0 reset
            } else {
#pragma unroll
                for (int j = 0; j < 8; ++j) mma_fp16(accB[j], a[0], b[j]);     // h0*d0
            }
#pragma unroll
            for (int j = 0; j < 8; ++j) mma_fp16(accS[j], a[1], b[j]);         // h1*d0
            // B component 1
#pragma unroll
            for (int j = 0; j < 8; ++j) {
                const char* bnp = base + 2 * ACOMP + BCOMP + (j * 8 + bn) * AROW;
                b[j][0] = *(const unsigned*)(bnp + (ks * 16 + kq) * 2);
                b[j][1] = *(const unsigned*)(bnp + (ks * 16 + kq + 8) * 2);
            }
#pragma unroll
            for (int j = 0; j < 8; ++j) mma_fp16(accS[j], a[0], b[j]);         // h0*d1
        }

        // ---- overlap: convert chunk ch+1 into the other buffer, prefetch ch+2 ----
        if (ch + 1 < NCH) {
            convert_store((ch + 1) & 1);
            if (ch + 2 < NCH) prefetch(ch + 2);
        }

        // ---- promote chunk partial with IEEE fp32 adds (overlaps tensor drain) ----
#pragma unroll
        for (int j = 0; j < 8; ++j)
#pragma unroll
            for (int q = 0; q < 4; ++q) acc[j][q] += accB[j][q];

        __syncthreads();   // converts of ch+1 complete; all LDS of ch complete
    }
    // fold in cross terms, undo 2^22 scaling
#pragma unroll
    for (int j = 0; j < 8; ++j)
#pragma unroll
        for (int q = 0; q < 4; ++q) acc[j][q] = (acc[j][q] + accS[j][q]) * DESCALE;

    // ---- accumulators -> Cs[row][col], stride 65 ----
    {
        const int cr = wid * 16 + (lane >> 2);
        const int cq = (lane & 3) * 2;
#pragma unroll
        for (int j = 0; j < 8; ++j) {
            Cs[cr * 65 + j * 8 + cq]           = acc[j][0];
            Cs[cr * 65 + j * 8 + cq + 1]       = acc[j][1];
            Cs[(cr + 8) * 65 + j * 8 + cq]     = acc[j][2];
            Cs[(cr + 8) * 65 + j * 8 + cq + 1] = acc[j][3];
        }
    }
    __syncthreads();

    // ---- per-token epilogue: softmax + top1/top2 + bucket insert ----
    if (tid < BM) {
        const int t = t0 + tid;
        const float* row = Cs + tid * 65;
        float m0 = row[0]; int i1 = 0;
#pragma unroll
        for (int e = 1; e < NE; ++e) { float l = row[e]; if (l > m0) { m0 = l; i1 = e; } }
        float m2 = -3.402823466e+38f; int i2 = 0;
#pragma unroll
        for (int e = 0; e < NE; ++e) {
            if (e == i1) continue;
            float l = row[e];
            if (l > m2) { m2 = l; i2 = e; }
        }
        float Z = 0.f;
#pragma unroll
        for (int e = 0; e < NE; ++e) Z += expf(row[e] - m0);
        const float p1 = 1.0f / Z;
        const float p2 = expf(m2 - m0) / Z;

        d_tok[t] = make_int4(i1, i2, __float_as_int(p1), __float_as_int(p2));
        const unsigned long long c =
            ((unsigned long long)__float_as_uint(p1) << 32) |
            (unsigned long long)(0xFFFFFFFFu - (unsigned)t);
        int pos1 = atomicAdd(&d_cnt1[i1], 1);
        d_bkt1[(size_t)i1 * NT + pos1] = c;
        int pos2 = atomicAdd(&d_cnt2[i2], 1);
        d_bkt2[(size_t)i2 * NT + pos2] = c;
    }
}

// ---------------- kernel 2: per-expert capacity ranking (drop-only writes) ----------------
__global__ __launch_bounds__(256) void k_rank() {
    __shared__ unsigned long long s[2048];   // 16KB
    const int bid    = blockIdx.x;
    const int e      = bid & 63;
    const bool second = (bid >= NE);
    const int n      = second ? d_cnt2[e] : d_cnt1[e];
    const unsigned long long* list = (second ? d_bkt2 : d_bkt1) + (size_t)e * NT;
    const int offset = second ? d_cnt1[e] : 0;
    unsigned char* keep = d_keep + (second ? NT : 0);

    if (n + offset <= CAP) return;             // all fit: keep already 1
    if (offset >= CAP) {                       // everything drops
        for (int i = threadIdx.x; i < n; i += blockDim.x)
            keep[(int)(0xFFFFFFFFu - (unsigned)list[i])] = 0;
        return;
    }
    if (n <= 2048) {
        for (int i = threadIdx.x; i < n; i += blockDim.x) s[i] = list[i];
        __syncthreads();
        for (int i = threadIdx.x; i < n; i += blockDim.x) {
            const unsigned long long ci = s[i];
            int r = 0;
            for (int j = 0; j < n; ++j) r += (s[j] > ci);
            if (r + offset >= CAP)
                keep[(int)(0xFFFFFFFFu - (unsigned)ci)] = 0;
        }
    } else {
        for (int i = threadIdx.x; i < n; i += blockDim.x) {
            const unsigned long long ci = list[i];
            int r = 0;
            for (int j = 0; j < n; ++j) r += (list[j] > ci);
            if (r + offset >= CAP)
                keep[(int)(0xFFFFFFFFu - (unsigned)ci)] = 0;
        }
    }
}

// ---------------- kernel 3: finalize outputs ----------------
__global__ __launch_bounds__(256) void k_finalize(float* __restrict__ out) {
    const int gid = blockIdx.x * blockDim.x + threadIdx.x;
    const int t = gid >> 4;
    const int c = gid & 15;
    const int4 rec = d_tok[t];
    const float p1 = __int_as_float(rec.z);
    const float p2 = __int_as_float(rec.w);
    const bool k1 = d_keep[t] != 0;
    const bool k2 = d_keep[NT + t] != 0;
    const float p1k = k1 ? p1 : 0.f;
    const float p2k = k2 ? p2 : 0.f;
    const float denom = fmaxf(p1k + p2k, 1.1920929e-07f);
    const float g1 = p1k / denom;
    const float g2 = p2k / denom;
    const float m1 = k1 ? 1.0f : 0.0f;

    const int e0 = c * 4;
    float4 m, p;
    m.x = (rec.x == e0 + 0) ? m1 : 0.f;
    m.y = (rec.x == e0 + 1) ? m1 : 0.f;
    m.z = (rec.x == e0 + 2) ? m1 : 0.f;
    m.w = (rec.x == e0 + 3) ? m1 : 0.f;
    p.x = (rec.x == e0 + 0) ? g1 : ((rec.y == e0 + 0) ? g2 : 0.f);
    p.y = (rec.x == e0 + 1) ? g1 : ((rec.y == e0 + 1) ? g2 : 0.f);
    p.z = (rec.x == e0 + 2) ? g1 : ((rec.y == e0 + 2) ? g2 : 0.f);
    p.w = (rec.x == e0 + 3) ? g1 : ((rec.y == e0 + 3) ? g2 : 0.f);

    float4* o = (float4*)out;
    o[(size_t)t * 16 + c] = m;
    o[(size_t)NT * 16 + (size_t)t * 16 + c] = p;
}

// ---------------- launch ----------------
extern "C" void kernel_launch(void* const* d_in, const int* in_sizes, int n_in,
                              void* d_out, int out_size) {
    (void)in_sizes; (void)n_in; (void)out_size;
    const float* X = (const float*)d_in[0];
    const float* W = (const float*)d_in[1];
    float* out = (float*)d_out;

    static bool attr_set = false;
    if (!attr_set) {
        cudaFuncSetAttribute(k_gemm_route, cudaFuncAttributeMaxDynamicSharedMemorySize, SMEM_BYTES);
        attr_set = true;
    }

    k_prepB<<<NCH, 256>>>(W);
    k_gemm_route<<<NCTA, 256, SMEM_BYTES>>>(X);
    k_rank<<<2 * NE, 256>>>();
    k_finalize<<<(NT * 16) / 256, 256>>>(out);
}

// round 15
// speedup vs baseline: 1.7228x; 1.2441x over previous
#include <cuda_runtime.h>
#include <cuda_fp16.h>
#include <cstdint>

// ---------------- problem constants ----------------
constexpr int NT  = 16384;   // tokens
constexpr int NH  = 2048;    // hidden
constexpr int NE  = 64;      // experts
constexpr int CAP = 512;     // 2*ceil(NT/NE)

constexpr int BM   = 128;    // tokens per CTA
constexpr int CH   = 32;     // k per chunk
constexpr int NCH  = NH / CH;       // 64 chunks
constexpr int NCTA = NT / BM;       // 128

constexpr int AROW  = 80;           // bytes per smem row: 32 fp16 (64B) + 16B pad
constexpr int ACOMP = BM * AROW;    // 10240 B per A component tile
constexpr int BCOMP = NE * AROW;    // 5120 B per B component tile
constexpr int BUFB  = 2 * ACOMP + 2 * BCOMP;  // 30720 per buffer
constexpr int SMEM_BYTES = 2 * BUFB;          // 61440 (dynamic)

constexpr int BCHUNK_BYTES = 2 * BCOMP;         // 10240 per chunk in d_Bp
constexpr int BCHUNK_I4    = BCHUNK_BYTES / 16; // 640

constexpr float SCALE   = 2048.0f;                // 2^11 (exact)
constexpr float DESCALE = 2.384185791015625e-07f; // 2^-22

// ---------------- device scratch ----------------
__device__ __align__(16) char d_Bp[NCH * BCHUNK_BYTES];  // pre-split, scaled B tiles
__device__ int4               d_tok[NT];
__device__ unsigned long long d_bkt1[NE * NT];
__device__ unsigned long long d_bkt2[NE * NT];
__device__ int                d_cnt1[NE];
__device__ int                d_cnt2[NE];
__device__ unsigned char      d_keep[2 * NT];

// ---------------- helpers ----------------
__device__ __forceinline__ void mma_fp16(float* d, const unsigned* a, const unsigned* b) {
    asm volatile("mma.sync.aligned.m16n8k16.row.col.f32.f16.f16.f32 "
        "{%0,%1,%2,%3}, {%4,%5,%6,%7}, {%8,%9}, {%0,%1,%2,%3};"
        : "+f"(d[0]), "+f"(d[1]), "+f"(d[2]), "+f"(d[3])
        : "r"(a[0]), "r"(a[1]), "r"(a[2]), "r"(a[3]), "r"(b[0]), "r"(b[1]));
}
__device__ __forceinline__ void mma_fp16_z(float* d, const unsigned* a, const unsigned* b) {
    asm volatile("mma.sync.aligned.m16n8k16.row.col.f32.f16.f16.f32 "
        "{%0,%1,%2,%3}, {%4,%5,%6,%7}, {%8,%9}, {%10,%10,%10,%10};"
        : "=f"(d[0]), "=f"(d[1]), "=f"(d[2]), "=f"(d[3])
        : "r"(a[0]), "r"(a[1]), "r"(a[2]), "r"(a[3]), "r"(b[0]), "r"(b[1]), "f"(0.f));
}
__device__ __forceinline__ unsigned h2u(__half2 h) { return *(unsigned*)&h; }

// ---------------- kernel P: split scaled W into 2 fp16 components ----------------
// Also zeroes counters and pre-initializes d_keep to 1 (k_rank writes only drops).
__global__ __launch_bounds__(256) void k_prepB(const float* __restrict__ W) {
    const int ch  = blockIdx.x;                 // 0..63
    const int tid = threadIdx.x;
    if (ch == 0 && tid < NE) { d_cnt1[tid] = 0; d_cnt2[tid] = 0; }
    {
        const int g = ch * 256 + tid;
        ((unsigned short*)d_keep)[g] = 0x0101;
    }
    const int e   = tid >> 2;                   // expert row
    const int kl0 = (tid & 3) * 8;              // k base within chunk
    char* dst = d_Bp + (size_t)ch * BCHUNK_BYTES + e * AROW + kl0 * 2;
#pragma unroll
    for (int i = 0; i < 8; i += 2) {
        const int k = ch * CH + kl0 + i;
        const float x0 = W[(size_t)k * NE + e] * SCALE;
        const float x1 = W[(size_t)(k + 1) * NE + e] * SCALE;
        const __half2 c0 = __floats2half2_rn(x0, x1);
        const float r0 = x0 - __low2float(c0), r1 = x1 - __high2float(c0);
        const __half2 c1 = __floats2half2_rn(r0, r1);
        *(unsigned*)(dst + i * 2)         = h2u(c0);
        *(unsigned*)(dst + BCOMP + i * 2) = h2u(c1);
    }
}

// ---------------- kernel 1: phase-shifted pipelined HMMA emulated-fp32 GEMM + routing ----------------
// Warps 0-3: [MMA ; convert].  Warps 4-7: [convert ; MMA].  SMSP pairs (w, w+4)
// therefore always have one warp issuing MMAs while the other's convert work
// fills the idle issue slots.
__global__ __launch_bounds__(256, 1) void k_gemm_route(const float* __restrict__ X) {
    extern __shared__ __align__(16) char smem[];
    float* Cs = (float*)smem;                 // [128][65] overlay after mainloop

    const int tid  = threadIdx.x;
    const int lane = tid & 31;
    const int wid  = tid >> 5;
    const int t0   = blockIdx.x * BM;

    const int xr = tid >> 1;
    const int xh = (tid & 1) * 16;
    const float4* xptr = (const float4*)(X + (size_t)(t0 + xr) * NH + xh);

    const int4* bsrc = (const int4*)d_Bp;

    float4 xv[4];
    int4   bv[3];
    float  accB[8][4];
    float  acc[8][4];    // master fp32 sum (IEEE FADD promoted)
    float  accS[8][4];   // persistent cross-term accumulator (~2^-12 scale)

    const int r0w = wid * 16 + (lane >> 2);   // A fragment row
    const int kq  = (lane & 3) * 2;           // fragment k offset
    const int bn  = lane >> 2;                // B fragment n offset within tile

    // convert current xv/bv regs into buffer `buf`
    auto convert_store = [&](int buf) {
        char* base = smem + buf * BUFB;
        char* arow = base + xr * AROW + xh * 2;
#pragma unroll
        for (int i = 0; i < 4; ++i) {
            const float4 v = xv[i];
            const float sx = v.x * SCALE, sy = v.y * SCALE;
            const float sz = v.z * SCALE, sw = v.w * SCALE;
            const __half2 a0 = __floats2half2_rn(sx, sy);
            const float r0 = sx - __low2float(a0), r1 = sy - __high2float(a0);
            const __half2 a1 = __floats2half2_rn(r0, r1);
            const __half2 b0 = __floats2half2_rn(sz, sw);
            const float q0 = sz - __low2float(b0), q1 = sw - __high2float(b0);
            const __half2 b1 = __floats2half2_rn(q0, q1);
            *(unsigned*)(arow + i * 8)             = h2u(a0);
            *(unsigned*)(arow + i * 8 + 4)         = h2u(b0);
            *(unsigned*)(arow + ACOMP + i * 8)     = h2u(a1);
            *(unsigned*)(arow + ACOMP + i * 8 + 4) = h2u(b1);
        }
        char* bbase = base + 2 * ACOMP;
#pragma unroll
        for (int j = 0; j < 3; ++j) {
            int i = tid + j * 256;
            if (i < BCHUNK_I4) *(int4*)(bbase + i * 16) = bv[j];
        }
    };

    // full MMA block for chunk ch (reads buf[ch&1])
    auto do_mmas = [&](int ch) {
        const char* base = smem + (ch & 1) * BUFB;
#pragma unroll
        for (int ks = 0; ks < 2; ++ks) {
            unsigned a[2][4];
#pragma unroll
            for (int c = 0; c < 2; ++c) {
                const char* ab = base + c * ACOMP;
                a[c][0] = *(const unsigned*)(ab + r0w * AROW + (ks * 16 + kq) * 2);
                a[c][1] = *(const unsigned*)(ab + (r0w + 8) * AROW + (ks * 16 + kq) * 2);
                a[c][2] = *(const unsigned*)(ab + r0w * AROW + (ks * 16 + kq + 8) * 2);
                a[c][3] = *(const unsigned*)(ab + (r0w + 8) * AROW + (ks * 16 + kq + 8) * 2);
            }
            unsigned b[8][2];
            // B component 0
#pragma unroll
            for (int j = 0; j < 8; ++j) {
                const char* bnp = base + 2 * ACOMP + (j * 8 + bn) * AROW;
                b[j][0] = *(const unsigned*)(bnp + (ks * 16 + kq) * 2);
                b[j][1] = *(const unsigned*)(bnp + (ks * 16 + kq + 8) * 2);
            }
            if (ks == 0) {
#pragma unroll
                for (int j = 0; j < 8; ++j) mma_fp16_z(accB[j], a[0], b[j]);   // h0*d0 reset
            } else {
#pragma unroll
                for (int j = 0; j < 8; ++j) mma_fp16(accB[j], a[0], b[j]);     // h0*d0
            }
#pragma unroll
            for (int j = 0; j < 8; ++j) mma_fp16(accS[j], a[1], b[j]);         // h1*d0
            // B component 1
#pragma unroll
            for (int j = 0; j < 8; ++j) {
                const char* bnp = base + 2 * ACOMP + BCOMP + (j * 8 + bn) * AROW;
                b[j][0] = *(const unsigned*)(bnp + (ks * 16 + kq) * 2);
                b[j][1] = *(const unsigned*)(bnp + (ks * 16 + kq + 8) * 2);
            }
#pragma unroll
            for (int j = 0; j < 8; ++j) mma_fp16(accS[j], a[0], b[j]);         // h0*d1
#pragma unroll
            for (int j = 0; j < 8; ++j) mma_fp16(accS[j], a[1], b[j]);         // h1*d1
        }
    };

    // convert+prefetch block for iteration ch (fills buf[(ch+1)&1])
    auto do_feed = [&](int ch) {
        if (ch + 1 < NCH) {
            convert_store((ch + 1) & 1);
            if (ch + 2 < NCH) {
#pragma unroll
                for (int i = 0; i < 4; ++i) xv[i] = xptr[(ch + 2) * 8 + i];
                const int4* bs2 = bsrc + (size_t)(ch + 2) * BCHUNK_I4;
#pragma unroll
                for (int j = 0; j < 3; ++j) { int i = tid + j * 256; if (i < BCHUNK_I4) bv[j] = bs2[i]; }
            }
        }
    };

    // prologue: chunk 0 -> regs -> buf0; prefetch chunk 1 regs
#pragma unroll
    for (int i = 0; i < 4; ++i) xv[i] = xptr[i];
#pragma unroll
    for (int j = 0; j < 3; ++j) { int i = tid + j * 256; if (i < BCHUNK_I4) bv[j] = bsrc[i]; }
    convert_store(0);
#pragma unroll
    for (int i = 0; i < 4; ++i) xv[i] = xptr[8 + i];
#pragma unroll
    for (int j = 0; j < 3; ++j) { int i = tid + j * 256; if (i < BCHUNK_I4) bv[j] = bsrc[BCHUNK_I4 + i]; }
    __syncthreads();

#pragma unroll
    for (int j = 0; j < 8; ++j)
#pragma unroll
        for (int q = 0; q < 4; ++q) { acc[j][q] = 0.f; accS[j][q] = 0.f; }

    for (int ch = 0; ch < NCH; ++ch) {
        if (wid < 4) { do_mmas(ch); do_feed(ch); }
        else         { do_feed(ch); do_mmas(ch); }

        // promote chunk partial with IEEE fp32 adds
#pragma unroll
        for (int j = 0; j < 8; ++j)
#pragma unroll
            for (int q = 0; q < 4; ++q) acc[j][q] += accB[j][q];

        __syncthreads();   // converts of ch+1 complete; all LDS of ch complete
    }
    // fold in cross terms, undo 2^22 scaling
#pragma unroll
    for (int j = 0; j < 8; ++j)
#pragma unroll
        for (int q = 0; q < 4; ++q) acc[j][q] = (acc[j][q] + accS[j][q]) * DESCALE;

    // ---- accumulators -> Cs[row][col], stride 65 ----
    {
        const int cr = wid * 16 + (lane >> 2);
        const int cq = (lane & 3) * 2;
#pragma unroll
        for (int j = 0; j < 8; ++j) {
            Cs[cr * 65 + j * 8 + cq]           = acc[j][0];
            Cs[cr * 65 + j * 8 + cq + 1]       = acc[j][1];
            Cs[(cr + 8) * 65 + j * 8 + cq]     = acc[j][2];
            Cs[(cr + 8) * 65 + j * 8 + cq + 1] = acc[j][3];
        }
    }
    __syncthreads();

    // ---- per-token epilogue: softmax + top1/top2 + bucket insert ----
    if (tid < BM) {
        const int t = t0 + tid;
        const float* row = Cs + tid * 65;
        float m0 = row[0]; int i1 = 0;
#pragma unroll
        for (int e = 1; e < NE; ++e) { float l = row[e]; if (l > m0) { m0 = l; i1 = e; } }
        float m2 = -3.402823466e+38f; int i2 = 0;
#pragma unroll
        for (int e = 0; e < NE; ++e) {
            if (e == i1) continue;
            float l = row[e];
            if (l > m2) { m2 = l; i2 = e; }
        }
        float Z = 0.f;
#pragma unroll
        for (int e = 0; e < NE; ++e) Z += expf(row[e] - m0);
        const float p1 = 1.0f / Z;
        const float p2 = expf(m2 - m0) / Z;

        d_tok[t] = make_int4(i1, i2, __float_as_int(p1), __float_as_int(p2));
        const unsigned long long c =
            ((unsigned long long)__float_as_uint(p1) << 32) |
            (unsigned long long)(0xFFFFFFFFu - (unsigned)t);
        int pos1 = atomicAdd(&d_cnt1[i1], 1);
        d_bkt1[(size_t)i1 * NT + pos1] = c;
        int pos2 = atomicAdd(&d_cnt2[i2], 1);
        d_bkt2[(size_t)i2 * NT + pos2] = c;
    }
}

// ---------------- kernel 2: per-expert capacity ranking (drop-only writes) ----------------
__global__ __launch_bounds__(256) void k_rank() {
    __shared__ unsigned long long s[2048];   // 16KB
    const int bid    = blockIdx.x;
    const int e      = bid & 63;
    const bool second = (bid >= NE);
    const int n      = second ? d_cnt2[e] : d_cnt1[e];
    const unsigned long long* list = (second ? d_bkt2 : d_bkt1) + (size_t)e * NT;
    const int offset = second ? d_cnt1[e] : 0;
    unsigned char* keep = d_keep + (second ? NT : 0);

    if (n + offset <= CAP) return;             // all fit: keep already 1
    if (offset >= CAP) {                       // everything drops
        for (int i = threadIdx.x; i < n; i += blockDim.x)
            keep[(int)(0xFFFFFFFFu - (unsigned)list[i])] = 0;
        return;
    }
    if (n <= 2048) {
        for (int i = threadIdx.x; i < n; i += blockDim.x) s[i] = list[i];
        __syncthreads();
        for (int i = threadIdx.x; i < n; i += blockDim.x) {
            const unsigned long long ci = s[i];
            int r = 0;
            for (int j = 0; j < n; ++j) r += (s[j] > ci);
            if (r + offset >= CAP)
                keep[(int)(0xFFFFFFFFu - (unsigned)ci)] = 0;
        }
    } else {
        for (int i = threadIdx.x; i < n; i += blockDim.x) {
            const unsigned long long ci = list[i];
            int r = 0;
            for (int j = 0; j < n; ++j) r += (list[j] > ci);
            if (r + offset >= CAP)
                keep[(int)(0xFFFFFFFFu - (unsigned)ci)] = 0;
        }
    }
}

// ---------------- kernel 3: finalize outputs ----------------
__global__ __launch_bounds__(256) void k_finalize(float* __restrict__ out) {
    const int gid = blockIdx.x * blockDim.x + threadIdx.x;
    const int t = gid >> 4;
    const int c = gid & 15;
    const int4 rec = d_tok[t];
    const float p1 = __int_as_float(rec.z);
    const float p2 = __int_as_float(rec.w);
    const bool k1 = d_keep[t] != 0;
    const bool k2 = d_keep[NT + t] != 0;
    const float p1k = k1 ? p1 : 0.f;
    const float p2k = k2 ? p2 : 0.f;
    const float denom = fmaxf(p1k + p2k, 1.1920929e-07f);
    const float g1 = p1k / denom;
    const float g2 = p2k / denom;
    const float m1 = k1 ? 1.0f : 0.0f;

    const int e0 = c * 4;
    float4 m, p;
    m.x = (rec.x == e0 + 0) ? m1 : 0.f;
    m.y = (rec.x == e0 + 1) ? m1 : 0.f;
    m.z = (rec.x == e0 + 2) ? m1 : 0.f;
    m.w = (rec.x == e0 + 3) ? m1 : 0.f;
    p.x = (rec.x == e0 + 0) ? g1 : ((rec.y == e0 + 0) ? g2 : 0.f);
    p.y = (rec.x == e0 + 1) ? g1 : ((rec.y == e0 + 1) ? g2 : 0.f);
    p.z = (rec.x == e0 + 2) ? g1 : ((rec.y == e0 + 2) ? g2 : 0.f);
    p.w = (rec.x == e0 + 3) ? g1 : ((rec.y == e0 + 3) ? g2 : 0.f);

    float4* o = (float4*)out;
    o[(size_t)t * 16 + c] = m;
    o[(size_t)NT * 16 + (size_t)t * 16 + c] = p;
}

// ---------------- launch ----------------
extern "C" void kernel_launch(void* const* d_in, const int* in_sizes, int n_in,
                              void* d_out, int out_size) {
    (void)in_sizes; (void)n_in; (void)out_size;
    const float* X = (const float*)d_in[0];
    const float* W = (const float*)d_in[1];
    float* out = (float*)d_out;

    static bool attr_set = false;
    if (!attr_set) {
        cudaFuncSetAttribute(k_gemm_route, cudaFuncAttributeMaxDynamicSharedMemorySize, SMEM_BYTES);
        attr_set = true;
    }

    k_prepB<<<NCH, 256>>>(W);
    k_gemm_route<<<NCTA, 256, SMEM_BYTES>>>(X);
    k_rank<<<2 * NE, 256>>>();
    k_finalize<<<(NT * 16) / 256, 256>>>(out);
}

// round 16
// speedup vs baseline: 1.8155x; 1.0538x over previous
#include <cuda_runtime.h>
#include <cuda_fp16.h>
#include <cstdint>

// ---------------- problem constants ----------------
constexpr int NT  = 16384;   // tokens
constexpr int NH  = 2048;    // hidden
constexpr int NE  = 64;      // experts
constexpr int CAP = 512;     // 2*ceil(NT/NE)

constexpr int BM   = 128;    // tokens per CTA
constexpr int CH   = 32;     // k per chunk
constexpr int NCH  = NH / CH;       // 64 chunks
constexpr int NCTA = NT / BM;       // 128

constexpr int AROW  = 80;           // bytes per smem row: 32 fp16 (64B) + 16B pad
constexpr int ACOMP = BM * AROW;    // 10240 B per A component tile
constexpr int BCOMP = NE * AROW;    // 5120 B per B component tile
constexpr int BUFB  = 2 * ACOMP + 2 * BCOMP;  // 30720 per buffer
constexpr int SMEM_BYTES = 2 * BUFB;          // 61440 (dynamic)

constexpr int BCHUNK_BYTES = 2 * BCOMP;         // 10240 per chunk in d_Bp
constexpr int BCHUNK_I4    = BCHUNK_BYTES / 16; // 640

constexpr float SCALE   = 2048.0f;                // 2^11 (exact)
constexpr float DESCALE = 2.384185791015625e-07f; // 2^-22

// ---------------- device scratch ----------------
__device__ __align__(16) char d_Bp[NCH * BCHUNK_BYTES];  // pre-split, scaled B tiles
__device__ int4               d_tok[NT];
__device__ unsigned long long d_bkt1[NE * NT];
__device__ unsigned long long d_bkt2[NE * NT];
__device__ int                d_cnt1[NE];
__device__ int                d_cnt2[NE];
__device__ unsigned char      d_keep[2 * NT];

// ---------------- helpers ----------------
__device__ __forceinline__ void mma_fp16(float* d, const unsigned* a, const unsigned* b) {
    asm volatile("mma.sync.aligned.m16n8k16.row.col.f32.f16.f16.f32 "
        "{%0,%1,%2,%3}, {%4,%5,%6,%7}, {%8,%9}, {%0,%1,%2,%3};"
        : "+f"(d[0]), "+f"(d[1]), "+f"(d[2]), "+f"(d[3])
        : "r"(a[0]), "r"(a[1]), "r"(a[2]), "r"(a[3]), "r"(b[0]), "r"(b[1]));
}
__device__ __forceinline__ void mma_fp16_z(float* d, const unsigned* a, const unsigned* b) {
    asm volatile("mma.sync.aligned.m16n8k16.row.col.f32.f16.f16.f32 "
        "{%0,%1,%2,%3}, {%4,%5,%6,%7}, {%8,%9}, {%10,%10,%10,%10};"
        : "=f"(d[0]), "=f"(d[1]), "=f"(d[2]), "=f"(d[3])
        : "r"(a[0]), "r"(a[1]), "r"(a[2]), "r"(a[3]), "r"(b[0]), "r"(b[1]), "f"(0.f));
}
__device__ __forceinline__ unsigned h2u(__half2 h) { return *(unsigned*)&h; }

// ---------------- kernel P: split scaled W into 2 fp16 components ----------------
// Also zeroes counters and pre-initializes d_keep to 1 (k_rank writes only drops).
__global__ __launch_bounds__(256) void k_prepB(const float* __restrict__ W) {
    const int ch  = blockIdx.x;                 // 0..63
    const int tid = threadIdx.x;
    if (ch == 0 && tid < NE) { d_cnt1[tid] = 0; d_cnt2[tid] = 0; }
    {
        const int g = ch * 256 + tid;
        ((unsigned short*)d_keep)[g] = 0x0101;
    }
    const int e   = tid >> 2;                   // expert row
    const int kl0 = (tid & 3) * 8;              // k base within chunk
    char* dst = d_Bp + (size_t)ch * BCHUNK_BYTES + e * AROW + kl0 * 2;
#pragma unroll
    for (int i = 0; i < 8; i += 2) {
        const int k = ch * CH + kl0 + i;
        const float x0 = W[(size_t)k * NE + e] * SCALE;
        const float x1 = W[(size_t)(k + 1) * NE + e] * SCALE;
        const __half2 c0 = __floats2half2_rn(x0, x1);
        const float r0 = x0 - __low2float(c0), r1 = x1 - __high2float(c0);
        const __half2 c1 = __floats2half2_rn(r0, r1);
        *(unsigned*)(dst + i * 2)         = h2u(c0);
        *(unsigned*)(dst + BCOMP + i * 2) = h2u(c1);
    }
}

// ---------------- kernel 1: pipelined HMMA emulated-fp32 GEMM + routing ----------------
// R10 structure (proven 86.2us) with the B-tile copy moved to cp.async (LDGSTS):
// fewer issue slots, 12 fewer live registers, same barriers and numerics.
__global__ __launch_bounds__(256, 1) void k_gemm_route(const float* __restrict__ X) {
    extern __shared__ __align__(16) char smem[];
    float* Cs = (float*)smem;                 // [128][65] overlay after mainloop

    const int tid  = threadIdx.x;
    const int lane = tid & 31;
    const int wid  = tid >> 5;
    const int t0   = blockIdx.x * BM;

    const int xr = tid >> 1;
    const int xh = (tid & 1) * 16;
    const float4* xptr = (const float4*)(X + (size_t)(t0 + xr) * NH + xh);

    const unsigned sbase = (unsigned)__cvta_generic_to_shared(smem);

    float4 xv[4];

    // async-copy chunk ch's B tiles into buffer `buf` (one commit group)
    auto cpasyncB = [&](int ch, int buf) {
        const char* gsrc = d_Bp + (size_t)ch * BCHUNK_BYTES;
        const unsigned dst = sbase + buf * BUFB + 2 * ACOMP;
#pragma unroll
        for (int j = 0; j < 3; ++j) {
            int i = tid + j * 256;
            if (i < BCHUNK_I4)
                asm volatile("cp.async.cg.shared.global [%0], [%1], 16;"
                             :: "r"(dst + i * 16), "l"(gsrc + (size_t)i * 16) : "memory");
        }
        asm volatile("cp.async.commit_group;" ::: "memory");
    };
    auto cpasync_wait = [&]() {
        asm volatile("cp.async.wait_group 0;" ::: "memory");
    };

    // convert current xv regs into buffer `buf` (A tiles only)
    auto convert_store = [&](int buf) {
        char* base = smem + buf * BUFB;
        char* arow = base + xr * AROW + xh * 2;
#pragma unroll
        for (int i = 0; i < 4; ++i) {
            const float4 v = xv[i];
            const float sx = v.x * SCALE, sy = v.y * SCALE;
            const float sz = v.z * SCALE, sw = v.w * SCALE;
            const __half2 a0 = __floats2half2_rn(sx, sy);
            const float r0 = sx - __low2float(a0), r1 = sy - __high2float(a0);
            const __half2 a1 = __floats2half2_rn(r0, r1);
            const __half2 b0 = __floats2half2_rn(sz, sw);
            const float q0 = sz - __low2float(b0), q1 = sw - __high2float(b0);
            const __half2 b1 = __floats2half2_rn(q0, q1);
            *(unsigned*)(arow + i * 8)             = h2u(a0);
            *(unsigned*)(arow + i * 8 + 4)         = h2u(b0);
            *(unsigned*)(arow + ACOMP + i * 8)     = h2u(a1);
            *(unsigned*)(arow + ACOMP + i * 8 + 4) = h2u(b1);
        }
    };

    // prologue: B chunk0 via cp.async; X chunk0 -> regs -> buf0; prefetch X chunk1
    cpasyncB(0, 0);
#pragma unroll
    for (int i = 0; i < 4; ++i) xv[i] = xptr[i];
    convert_store(0);
#pragma unroll
    for (int i = 0; i < 4; ++i) xv[i] = xptr[8 + i];
    cpasync_wait();
    __syncthreads();

    float acc[8][4];    // master fp32 sum (IEEE FADD promoted)
    float accS[8][4];   // persistent cross-term accumulator (~2^-12 scale)
#pragma unroll
    for (int j = 0; j < 8; ++j)
#pragma unroll
        for (int q = 0; q < 4; ++q) { acc[j][q] = 0.f; accS[j][q] = 0.f; }

    const int r0w = wid * 16 + (lane >> 2);   // A fragment row
    const int kq  = (lane & 3) * 2;           // fragment k offset
    const int bn  = lane >> 2;                // B fragment n offset within tile

    for (int ch = 0; ch < NCH; ++ch) {
        const char* base = smem + (ch & 1) * BUFB;
        const bool more = (ch + 1 < NCH);

        // issue next chunk's B async copy early (latency covered by MMA block)
        if (more) cpasyncB(ch + 1, (ch + 1) & 1);

        // ---- MMAs on buf[ch&1]: h0d0 -> accB (fresh); h1d0, h0d1, h1d1 -> accS ----
        float accB[8][4];
#pragma unroll
        for (int ks = 0; ks < 2; ++ks) {
            unsigned a[2][4];
#pragma unroll
            for (int c = 0; c < 2; ++c) {
                const char* ab = base + c * ACOMP;
                a[c][0] = *(const unsigned*)(ab + r0w * AROW + (ks * 16 + kq) * 2);
                a[c][1] = *(const unsigned*)(ab + (r0w + 8) * AROW + (ks * 16 + kq) * 2);
                a[c][2] = *(const unsigned*)(ab + r0w * AROW + (ks * 16 + kq + 8) * 2);
                a[c][3] = *(const unsigned*)(ab + (r0w + 8) * AROW + (ks * 16 + kq + 8) * 2);
            }
            unsigned b[8][2];
            // B component 0
#pragma unroll
            for (int j = 0; j < 8; ++j) {
                const char* bnp = base + 2 * ACOMP + (j * 8 + bn) * AROW;
                b[j][0] = *(const unsigned*)(bnp + (ks * 16 + kq) * 2);
                b[j][1] = *(const unsigned*)(bnp + (ks * 16 + kq + 8) * 2);
            }
            if (ks == 0) {
#pragma unroll
                for (int j = 0; j < 8; ++j) mma_fp16_z(accB[j], a[0], b[j]);   // h0*d0 reset
            } else {
#pragma unroll
                for (int j = 0; j < 8; ++j) mma_fp16(accB[j], a[0], b[j]);     // h0*d0
            }
#pragma unroll
            for (int j = 0; j < 8; ++j) mma_fp16(accS[j], a[1], b[j]);         // h1*d0
            // B component 1
#pragma unroll
            for (int j = 0; j < 8; ++j) {
                const char* bnp = base + 2 * ACOMP + BCOMP + (j * 8 + bn) * AROW;
                b[j][0] = *(const unsigned*)(bnp + (ks * 16 + kq) * 2);
                b[j][1] = *(const unsigned*)(bnp + (ks * 16 + kq + 8) * 2);
            }
#pragma unroll
            for (int j = 0; j < 8; ++j) mma_fp16(accS[j], a[0], b[j]);         // h0*d1
#pragma unroll
            for (int j = 0; j < 8; ++j) mma_fp16(accS[j], a[1], b[j]);         // h1*d1
        }

        // ---- overlap: convert chunk ch+1 A tiles, prefetch X chunk ch+2 ----
        if (more) {
            convert_store((ch + 1) & 1);
            if (ch + 2 < NCH) {
#pragma unroll
                for (int i = 0; i < 4; ++i) xv[i] = xptr[(ch + 2) * 8 + i];
            }
        }

        // ---- promote chunk partial with IEEE fp32 adds (overlaps tensor drain) ----
#pragma unroll
        for (int j = 0; j < 8; ++j)
#pragma unroll
            for (int q = 0; q < 4; ++q) acc[j][q] += accB[j][q];

        if (more) cpasync_wait();   // B of chunk ch+1 landed
        __syncthreads();            // converts of ch+1 complete; all LDS of ch complete
    }
    // fold in cross terms, undo 2^22 scaling
#pragma unroll
    for (int j = 0; j < 8; ++j)
#pragma unroll
        for (int q = 0; q < 4; ++q) acc[j][q] = (acc[j][q] + accS[j][q]) * DESCALE;

    // ---- accumulators -> Cs[row][col], stride 65 ----
    {
        const int cr = wid * 16 + (lane >> 2);
        const int cq = (lane & 3) * 2;
#pragma unroll
        for (int j = 0; j < 8; ++j) {
            Cs[cr * 65 + j * 8 + cq]           = acc[j][0];
            Cs[cr * 65 + j * 8 + cq + 1]       = acc[j][1];
            Cs[(cr + 8) * 65 + j * 8 + cq]     = acc[j][2];
            Cs[(cr + 8) * 65 + j * 8 + cq + 1] = acc[j][3];
        }
    }
    __syncthreads();

    // ---- per-token epilogue: softmax + top1/top2 + bucket insert ----
    if (tid < BM) {
        const int t = t0 + tid;
        const float* row = Cs + tid * 65;
        float m0 = row[0]; int i1 = 0;
#pragma unroll
        for (int e = 1; e < NE; ++e) { float l = row[e]; if (l > m0) { m0 = l; i1 = e; } }
        float m2 = -3.402823466e+38f; int i2 = 0;
#pragma unroll
        for (int e = 0; e < NE; ++e) {
            if (e == i1) continue;
            float l = row[e];
            if (l > m2) { m2 = l; i2 = e; }
        }
        float Z = 0.f;
#pragma unroll
        for (int e = 0; e < NE; ++e) Z += expf(row[e] - m0);
        const float p1 = 1.0f / Z;
        const float p2 = expf(m2 - m0) / Z;

        d_tok[t] = make_int4(i1, i2, __float_as_int(p1), __float_as_int(p2));
        const unsigned long long c =
            ((unsigned long long)__float_as_uint(p1) << 32) |
            (unsigned long long)(0xFFFFFFFFu - (unsigned)t);
        int pos1 = atomicAdd(&d_cnt1[i1], 1);
        d_bkt1[(size_t)i1 * NT + pos1] = c;
        int pos2 = atomicAdd(&d_cnt2[i2], 1);
        d_bkt2[(size_t)i2 * NT + pos2] = c;
    }
}

// ---------------- kernel 2: per-expert capacity ranking (drop-only writes) ----------------
__global__ __launch_bounds__(256) void k_rank() {
    __shared__ unsigned long long s[2048];   // 16KB
    const int bid    = blockIdx.x;
    const int e      = bid & 63;
    const bool second = (bid >= NE);
    const int n      = second ? d_cnt2[e] : d_cnt1[e];
    const unsigned long long* list = (second ? d_bkt2 : d_bkt1) + (size_t)e * NT;
    const int offset = second ? d_cnt1[e] : 0;
    unsigned char* keep = d_keep + (second ? NT : 0);

    if (n + offset <= CAP) return;             // all fit: keep already 1
    if (offset >= CAP) {                       // everything drops
        for (int i = threadIdx.x; i < n; i += blockDim.x)
            keep[(int)(0xFFFFFFFFu - (unsigned)list[i])] = 0;
        return;
    }
    if (n <= 2048) {
        for (int i = threadIdx.x; i < n; i += blockDim.x) s[i] = list[i];
        __syncthreads();
        for (int i = threadIdx.x; i < n; i += blockDim.x) {
            const unsigned long long ci = s[i];
            int r = 0;
            for (int j = 0; j < n; ++j) r += (s[j] > ci);
            if (r + offset >= CAP)
                keep[(int)(0xFFFFFFFFu - (unsigned)ci)] = 0;
        }
    } else {
        for (int i = threadIdx.x; i < n; i += blockDim.x) {
            const unsigned long long ci = list[i];
            int r = 0;
            for (int j = 0; j < n; ++j) r += (list[j] > ci);
            if (r + offset >= CAP)
                keep[(int)(0xFFFFFFFFu - (unsigned)ci)] = 0;
        }
    }
}

// ---------------- kernel 3: finalize outputs ----------------
__global__ __launch_bounds__(256) void k_finalize(float* __restrict__ out) {
    const int gid = blockIdx.x * blockDim.x + threadIdx.x;
    const int t = gid >> 4;
    const int c = gid & 15;
    const int4 rec = d_tok[t];
    const float p1 = __int_as_float(rec.z);
    const float p2 = __int_as_float(rec.w);
    const bool k1 = d_keep[t] != 0;
    const bool k2 = d_keep[NT + t] != 0;
    const float p1k = k1 ? p1 : 0.f;
    const float p2k = k2 ? p2 : 0.f;
    const float denom = fmaxf(p1k + p2k, 1.1920929e-07f);
    const float g1 = p1k / denom;
    const float g2 = p2k / denom;
    const float m1 = k1 ? 1.0f : 0.0f;

    const int e0 = c * 4;
    float4 m, p;
    m.x = (rec.x == e0 + 0) ? m1 : 0.f;
    m.y = (rec.x == e0 + 1) ? m1 : 0.f;
    m.z = (rec.x == e0 + 2) ? m1 : 0.f;
    m.w = (rec.x == e0 + 3) ? m1 : 0.f;
    p.x = (rec.x == e0 + 0) ? g1 : ((rec.y == e0 + 0) ? g2 : 0.f);
    p.y = (rec.x == e0 + 1) ? g1 : ((rec.y == e0 + 1) ? g2 : 0.f);
    p.z = (rec.x == e0 + 2) ? g1 : ((rec.y == e0 + 2) ? g2 : 0.f);
    p.w = (rec.x == e0 + 3) ? g1 : ((rec.y == e0 + 3) ? g2 : 0.f);

    float4* o = (float4*)out;
    o[(size_t)t * 16 + c] = m;
    o[(size_t)NT * 16 + (size_t)t * 16 + c] = p;
}

// ---------------- launch ----------------
extern "C" void kernel_launch(void* const* d_in, const int* in_sizes, int n_in,
                              void* d_out, int out_size) {
    (void)in_sizes; (void)n_in; (void)out_size;
    const float* X = (const float*)d_in[0];
    const float* W = (const float*)d_in[1];
    float* out = (float*)d_out;

    static bool attr_set = false;
    if (!attr_set) {
        cudaFuncSetAttribute(k_gemm_route, cudaFuncAttributeMaxDynamicSharedMemorySize, SMEM_BYTES);
        attr_set = true;
    }

    k_prepB<<<NCH, 256>>>(W);
    k_gemm_route<<<NCTA, 256, SMEM_BYTES>>>(X);
    k_rank<<<2 * NE, 256>>>();
    k_finalize<<<(NT * 16) / 256, 256>>>(out);
}